// round 15
// baseline (speedup 1.0000x reference)
#include <cuda_runtime.h>
#include <cuda_fp16.h>
#include <cuda_bf16.h>

#define NN 50000
#define NE 800000
#define SCAN_B 98          // ceil(50000/512)

// ---------------- scratch (device globals; no allocation allowed) ----------------
__device__ __half g_f1h[(size_t)NN * 256]; // layer1 projected features (fp16 storage)
__device__ __half g_f2h[(size_t)NN * 32];  // layer2 projected features (fp16 storage)
__device__ float g_el1[NN * 8];
__device__ float g_er1[NN * 8];
__device__ float g_el2[NN];
__device__ float g_er2[NN];
__device__ int   g_offs[NN + 1];
__device__ int   g_cursor[NN];             // zero at call entry (load-time init + tail reset)
__device__ int   g_csr_src[NE];
__device__ unsigned long long g_lb[SCAN_B];// lookback state; zero at call entry

// ---------------- f32x2 packed-FMA helpers ----------------
__device__ __forceinline__ unsigned long long pk2(float x, float y) {
    unsigned long long r;
    asm("mov.b64 %0, {%1, %2};" : "=l"(r) : "f"(x), "f"(y));
    return r;
}
__device__ __forceinline__ void upk2(unsigned long long v, float& x, float& y) {
    asm("mov.b64 {%0, %1}, %2;" : "=f"(x), "=f"(y) : "l"(v));
}
__device__ __forceinline__ void fma2(unsigned long long& c, unsigned long long a, unsigned long long b) {
    asm("fma.rn.f32x2 %0, %1, %2, %0;" : "+l"(c) : "l"(a), "l"(b));
}

__device__ __forceinline__ float lrelu(float e) { return e > 0.f ? e : 0.2f * e; }
__device__ __forceinline__ float elu(float v)   { return v > 0.f ? v : expm1f(v); }

// ascending bitonic sort of 32 values across a warp (pad with INT_MAX)
__device__ __forceinline__ int warp_bitonic32(int v, int lane) {
    #pragma unroll
    for (int k = 2; k <= 32; k <<= 1) {
        #pragma unroll
        for (int j = k >> 1; j > 0; j >>= 1) {
            int other = __shfl_xor_sync(0xffffffffu, v, j);
            bool up = ((lane & k) == 0);
            bool keepMin = (((lane & j) == 0) == up);
            v = keepMin ? min(v, other) : max(v, other);
        }
    }
    return v;
}

// ---------------- CSR build ----------------
__global__ void k_degree(const int* __restrict__ dst) {
    for (int e = blockIdx.x * blockDim.x + threadIdx.x; e < NE; e += gridDim.x * blockDim.x)
        atomicAdd(&g_cursor[dst[e]], 1);
}

// single-pass exclusive scan with decoupled lookback (98 blocks, all resident)
__global__ __launch_bounds__(512) void k_scan_lb() {
    __shared__ int sh[512];
    __shared__ int s_prev;
    int t = threadIdx.x, b = blockIdx.x;
    int i = b * 512 + t;
    int v = (i < NN) ? g_cursor[i] : 0;
    sh[t] = v;
    __syncthreads();
    #pragma unroll
    for (int o = 1; o < 512; o <<= 1) {
        int add = (t >= o) ? sh[t - o] : 0;
        __syncthreads();
        sh[t] += add;
        __syncthreads();
    }
    int total = sh[511];
    if (t < 32) {
        if (b == 0) {
            if (t == 0) {
                atomicExch(&g_lb[0], (2ull << 32) | (unsigned)total);
                s_prev = 0;
            }
        } else {
            if (t == 0) atomicExch(&g_lb[b], (1ull << 32) | (unsigned)total);
            __syncwarp();
            int running = 0;
            int j = b - 1;
            while (true) {
                int idx = j - t;
                unsigned long long s = (idx >= 0) ? atomicAdd(&g_lb[idx], 0ull) : (2ull << 32);
                unsigned f = (unsigned)(s >> 32);
                if (!__all_sync(0xffffffffu, f != 0)) continue;
                unsigned m2 = __ballot_sync(0xffffffffu, f == 2);
                int stop = m2 ? (__ffs(m2) - 1) : 31;
                int contrib = (t <= stop) ? (int)(unsigned)(s & 0xffffffffu) : 0;
                #pragma unroll
                for (int o = 16; o; o >>= 1) contrib += __shfl_xor_sync(0xffffffffu, contrib, o);
                running += contrib;
                if (m2) break;
                j -= 32;
            }
            if (t == 0) {
                atomicExch(&g_lb[b], (2ull << 32) | (unsigned)(running + total));
                s_prev = running;
            }
        }
    }
    __syncthreads();
    int prev = s_prev;
    if (i < NN) {
        int ex = prev + sh[t] - v;
        g_offs[i] = ex;
        g_cursor[i] = ex;
    }
    if (i == NN) g_offs[NN] = NE;
}

__global__ void k_scatter(const int* __restrict__ src, const int* __restrict__ dst) {
    for (int e = blockIdx.x * blockDim.x + threadIdx.x; e < NE; e += gridDim.x * blockDim.x) {
        int p = atomicAdd(&g_cursor[dst[e]], 1);
        g_csr_src[p] = src[e];
    }
}

// tail reset: leaves cursor + lookback state zeroed for the next call
__global__ void k_reset() {
    int i = blockIdx.x * blockDim.x + threadIdx.x;
    if (i < NN) g_cursor[i] = 0;
    if (i < SCAN_B) g_lb[i] = 0ull;
}

// ---------------- GEMM1 + fused logits: f1h = half(X @ W1); el1/er1 fp32 ----------------
__global__ __launch_bounds__(256, 2) void k_gemm1(const float* __restrict__ A, const float* __restrict__ B,
                                                  const float* __restrict__ al1, const float* __restrict__ ar1) {
    __shared__ float As[2][16][132];
    __shared__ float Bs[2][16][128];
    int tid = threadIdx.x;
    int tx = tid & 15, ty = tid >> 4;
    int bn = blockIdx.x * 128;
    int bm = blockIdx.y * 128;

    int arow = tid >> 2, ac4 = tid & 3;
    int arow2 = (tid + 256) >> 2, ac42 = (tid + 256) & 3;
    int bkr = tid >> 5, bc4 = tid & 31;
    int bkr2 = (tid + 256) >> 5, bc42 = (tid + 256) & 31;

    int hA = (bn >> 5) + (tx >> 3);
    int hB = hA + 2;
    int cm = (tx & 7) * 4;
    float4 alA = *(const float4*)(al1 + hA * 32 + cm);
    float4 arA = *(const float4*)(ar1 + hA * 32 + cm);
    float4 alB = *(const float4*)(al1 + hB * 32 + cm);
    float4 arB = *(const float4*)(ar1 + hB * 32 + cm);

    unsigned long long c[8][4];
    #pragma unroll
    for (int i = 0; i < 8; i++)
        #pragma unroll
        for (int j = 0; j < 4; j++) c[i][j] = 0ull;

    float4 ra0, ra1, rb0, rb1;
    {
        int gr0 = bm + arow, gr1 = bm + arow2;
        ra0 = (gr0 < NN) ? *(const float4*)(A + (size_t)gr0 * 128 + ac4 * 4) : make_float4(0.f,0.f,0.f,0.f);
        ra1 = (gr1 < NN) ? *(const float4*)(A + (size_t)gr1 * 128 + ac42 * 4) : make_float4(0.f,0.f,0.f,0.f);
        rb0 = *(const float4*)(B + (size_t)bkr  * 256 + bn + bc4  * 4);
        rb1 = *(const float4*)(B + (size_t)bkr2 * 256 + bn + bc42 * 4);
        As[0][ac4 * 4 + 0][arow] = ra0.x; As[0][ac4 * 4 + 1][arow] = ra0.y;
        As[0][ac4 * 4 + 2][arow] = ra0.z; As[0][ac4 * 4 + 3][arow] = ra0.w;
        As[0][ac42 * 4 + 0][arow2] = ra1.x; As[0][ac42 * 4 + 1][arow2] = ra1.y;
        As[0][ac42 * 4 + 2][arow2] = ra1.z; As[0][ac42 * 4 + 3][arow2] = ra1.w;
        *(float4*)&Bs[0][bkr][bc4 * 4] = rb0;
        *(float4*)&Bs[0][bkr2][bc42 * 4] = rb1;
    }
    __syncthreads();

    #pragma unroll
    for (int t = 0; t < 8; t++) {
        int cur = t & 1;
        if (t < 7) {
            int kt = (t + 1) * 16;
            int gr0 = bm + arow, gr1 = bm + arow2;
            ra0 = (gr0 < NN) ? *(const float4*)(A + (size_t)gr0 * 128 + kt + ac4 * 4) : make_float4(0.f,0.f,0.f,0.f);
            ra1 = (gr1 < NN) ? *(const float4*)(A + (size_t)gr1 * 128 + kt + ac42 * 4) : make_float4(0.f,0.f,0.f,0.f);
            rb0 = *(const float4*)(B + (size_t)(kt + bkr)  * 256 + bn + bc4  * 4);
            rb1 = *(const float4*)(B + (size_t)(kt + bkr2) * 256 + bn + bc42 * 4);
        }
        #pragma unroll
        for (int k = 0; k < 16; k++) {
            float4 a0 = *(const float4*)&As[cur][k][ty * 4];
            float4 a1 = *(const float4*)&As[cur][k][64 + ty * 4];
            float4 b0 = *(const float4*)&Bs[cur][k][tx * 4];
            float4 b1 = *(const float4*)&Bs[cur][k][64 + tx * 4];
            float av[8] = {a0.x, a0.y, a0.z, a0.w, a1.x, a1.y, a1.z, a1.w};
            unsigned long long bp[4];
            bp[0] = pk2(b0.x, b0.y); bp[1] = pk2(b0.z, b0.w);
            bp[2] = pk2(b1.x, b1.y); bp[3] = pk2(b1.z, b1.w);
            #pragma unroll
            for (int i = 0; i < 8; i++) {
                unsigned long long aa = pk2(av[i], av[i]);
                fma2(c[i][0], aa, bp[0]);
                fma2(c[i][1], aa, bp[1]);
                fma2(c[i][2], aa, bp[2]);
                fma2(c[i][3], aa, bp[3]);
            }
        }
        if (t < 7) {
            int nxt = cur ^ 1;
            As[nxt][ac4 * 4 + 0][arow] = ra0.x; As[nxt][ac4 * 4 + 1][arow] = ra0.y;
            As[nxt][ac4 * 4 + 2][arow] = ra0.z; As[nxt][ac4 * 4 + 3][arow] = ra0.w;
            As[nxt][ac42 * 4 + 0][arow2] = ra1.x; As[nxt][ac42 * 4 + 1][arow2] = ra1.y;
            As[nxt][ac42 * 4 + 2][arow2] = ra1.z; As[nxt][ac42 * 4 + 3][arow2] = ra1.w;
            *(float4*)&Bs[nxt][bkr][bc4 * 4] = rb0;
            *(float4*)&Bs[nxt][bkr2][bc42 * 4] = rb1;
        }
        __syncthreads();
    }

    int lane = tid & 31;
    #pragma unroll
    for (int i = 0; i < 8; i++) {
        int mloc = (i < 4) ? (ty * 4 + i) : (64 + ty * 4 + i - 4);
        int gr = bm + mloc;
        float v0, v1, v2, v3, v4, v5, v6, v7;
        upk2(c[i][0], v0, v1); upk2(c[i][1], v2, v3);
        upk2(c[i][2], v4, v5); upk2(c[i][3], v6, v7);
        if (gr < NN) {
            __half2 p0 = __floats2half2_rn(v0, v1);
            __half2 p1 = __floats2half2_rn(v2, v3);
            __half2 p2 = __floats2half2_rn(v4, v5);
            __half2 p3 = __floats2half2_rn(v6, v7);
            uint2 s0 = make_uint2(*(unsigned*)&p0, *(unsigned*)&p1);
            uint2 s1 = make_uint2(*(unsigned*)&p2, *(unsigned*)&p3);
            *(uint2*)(g_f1h + (size_t)gr * 256 + bn + tx * 4)      = s0;
            *(uint2*)(g_f1h + (size_t)gr * 256 + bn + 64 + tx * 4) = s1;
        }
        float elA = v0 * alA.x + v1 * alA.y + v2 * alA.z + v3 * alA.w;
        float erA = v0 * arA.x + v1 * arA.y + v2 * arA.z + v3 * arA.w;
        float elB = v4 * alB.x + v5 * alB.y + v6 * alB.z + v7 * alB.w;
        float erB = v4 * arB.x + v5 * arB.y + v6 * arB.z + v7 * arB.w;
        #pragma unroll
        for (int o = 1; o < 8; o <<= 1) {
            elA += __shfl_xor_sync(0xffffffffu, elA, o);
            erA += __shfl_xor_sync(0xffffffffu, erA, o);
            elB += __shfl_xor_sync(0xffffffffu, elB, o);
            erB += __shfl_xor_sync(0xffffffffu, erB, o);
        }
        if ((lane & 7) == 0 && gr < NN) {
            g_el1[gr * 8 + hA] = elA;  g_er1[gr * 8 + hA] = erA;
            g_el1[gr * 8 + hB] = elB;  g_er1[gr * 8 + hB] = erB;
        }
    }
}

// ---------------- fused layer-1 aggregation + layer-2 projection ----------------
// deg>32 fallback path helper (lanes<8 compute weights)
__device__ __forceinline__ void agg1_edge(int s, int lane, int hsel, float er8,
                                          float4& a0, float4& a1, float& wsum) {
    float w = 0.f;
    if (lane < 8) {
        w = __expf(lrelu(__ldg(&g_el1[s * 8 + lane]) + er8));
        wsum += w;
    }
    uint4 raw = __ldg((const uint4*)g_f1h + (size_t)s * 32 + lane);
    float wh = __shfl_sync(0xffffffffu, w, hsel);
    __half2 h0 = *(__half2*)&raw.x, h1 = *(__half2*)&raw.y;
    __half2 h2 = *(__half2*)&raw.z, h3 = *(__half2*)&raw.w;
    float2 f0 = __half22float2(h0), f1 = __half22float2(h1);
    float2 f2 = __half22float2(h2), f3 = __half22float2(h3);
    a0.x = fmaf(wh, f0.x, a0.x); a0.y = fmaf(wh, f0.y, a0.y);
    a0.z = fmaf(wh, f1.x, a0.z); a0.w = fmaf(wh, f1.y, a0.w);
    a1.x = fmaf(wh, f2.x, a1.x); a1.y = fmaf(wh, f2.y, a1.y);
    a1.z = fmaf(wh, f3.x, a1.z); a1.w = fmaf(wh, f3.y, a1.w);
}

__global__ __launch_bounds__(256) void k_agg1g2(const float* __restrict__ b1,
                                                const float* __restrict__ W2,
                                                const float* __restrict__ al2,
                                                const float* __restrict__ ar2) {
    __shared__ ulonglong2 sWT[32][65];   // [c][k4] K-packed W2 pairs; pad 65 -> conflict-free
    __shared__ float sH[8][256];         // per-warp h row staging
    __shared__ float sal[32], sar[32];
    int tid = threadIdx.x;
    for (int idx = tid; idx < 2048; idx += 256) {
        int k4 = idx >> 5, cc = idx & 31;
        float w0 = W2[(k4 * 4 + 0) * 32 + cc];
        float w1 = W2[(k4 * 4 + 1) * 32 + cc];
        float w2 = W2[(k4 * 4 + 2) * 32 + cc];
        float w3 = W2[(k4 * 4 + 3) * 32 + cc];
        ulonglong2 p; p.x = pk2(w0, w1); p.y = pk2(w2, w3);
        sWT[cc][k4] = p;
    }
    if (tid < 32) { sal[tid] = al2[tid]; sar[tid] = ar2[tid]; }
    __syncthreads();

    int lane = tid & 31;
    int w = tid >> 5;
    int gwarp = (blockIdx.x * blockDim.x + tid) >> 5;
    int nwarps = (gridDim.x * blockDim.x) >> 5;
    float4 bb0 = *(const float4*)(b1 + lane * 8);
    float4 bb1 = *(const float4*)(b1 + lane * 8 + 4);
    int hsel = lane >> 2;       // head owning this lane's 8 feature columns
    int grp  = lane >> 3;       // 4-edge-group id for batched weight gather
    int hmod = lane & 7;        // head for batched weight gather
    float salc = sal[lane], sarc = sar[lane];

    // prefetch first node's offsets
    int beg = 0, end = 0;
    if (gwarp < NN) { beg = __ldg(&g_offs[gwarp]); end = __ldg(&g_offs[gwarp + 1]); }

    for (int n = gwarp; n < NN; n += nwarps) {
        int deg = end - beg;
        int curBeg = beg;
        int nn2 = n + nwarps;
        if (nn2 < NN) { beg = __ldg(&g_offs[nn2]); end = __ldg(&g_offs[nn2 + 1]); }

        float4 o0, o1;
        if (deg == 0) {
            o0 = make_float4(elu(bb0.x), elu(bb0.y), elu(bb0.z), elu(bb0.w));
            o1 = make_float4(elu(bb1.x), elu(bb1.y), elu(bb1.z), elu(bb1.w));
        } else {
            float er8 = g_er1[n * 8 + hmod];   // all lanes: er for head (lane&7)
            float4 acc0 = make_float4(0.f, 0.f, 0.f, 0.f);
            float4 acc1 = make_float4(0.f, 0.f, 0.f, 0.f);
            float wsum = 0.f;

            if (deg <= 32) {
                int myv = (lane < deg) ? __ldg(&g_csr_src[curBeg + lane]) : 0x7fffffff;
                myv = warp_bitonic32(myv, lane);
                for (int i = 0; i < deg; i += 4) {
                    // batched weight gather: lane l covers edge i+(l>>3), head l&7
                    int eidx = i + grp;
                    int sg = __shfl_sync(0xffffffffu, myv, eidx & 31);
                    float wv = 0.f;
                    if (eidx < deg)
                        wv = __expf(lrelu(__ldg(&g_el1[sg * 8 + hmod]) + er8));
                    wsum += wv;
                    // feature gather + weighted accumulate, 4 edges
                    #pragma unroll
                    for (int j = 0; j < 4; j++) {
                        if (i + j < deg) {
                            int s = __shfl_sync(0xffffffffu, myv, i + j);
                            uint4 raw = __ldg((const uint4*)g_f1h + (size_t)s * 32 + lane);
                            float wh = __shfl_sync(0xffffffffu, wv, j * 8 + hsel);
                            __half2 h0 = *(__half2*)&raw.x, h1 = *(__half2*)&raw.y;
                            __half2 h2 = *(__half2*)&raw.z, h3 = *(__half2*)&raw.w;
                            float2 f0 = __half22float2(h0), f1 = __half22float2(h1);
                            float2 f2 = __half22float2(h2), f3 = __half22float2(h3);
                            acc0.x = fmaf(wh, f0.x, acc0.x); acc0.y = fmaf(wh, f0.y, acc0.y);
                            acc0.z = fmaf(wh, f1.x, acc0.z); acc0.w = fmaf(wh, f1.y, acc0.w);
                            acc1.x = fmaf(wh, f2.x, acc1.x); acc1.y = fmaf(wh, f2.y, acc1.y);
                            acc1.z = fmaf(wh, f3.x, acc1.z); acc1.w = fmaf(wh, f3.y, acc1.w);
                        }
                    }
                }
                // reduce wsum over the 4 edge groups; lane l ends with total for head l&7
                wsum += __shfl_xor_sync(0xffffffffu, wsum, 8);
                wsum += __shfl_xor_sync(0xffffffffu, wsum, 16);
            } else {
                int curEnd = curBeg + deg;
                if (lane == 0) {   // rare: deterministic in-place global insertion sort
                    for (int i = curBeg + 1; i < curEnd; i++) {
                        int key = g_csr_src[i];
                        int j = i - 1;
                        while (j >= curBeg && g_csr_src[j] > key) { g_csr_src[j + 1] = g_csr_src[j]; j--; }
                        g_csr_src[j + 1] = key;
                    }
                }
                __syncwarp();
                for (int i = curBeg; i < curEnd; i++) {
                    int s0 = g_csr_src[i];
                    agg1_edge(s0, lane, hsel, er8, acc0, acc1, wsum);
                }
            }

            float d = __shfl_sync(0xffffffffu, wsum, hsel);
            float inv = 1.f / d;
            o0 = make_float4(elu(acc0.x * inv + bb0.x), elu(acc0.y * inv + bb0.y),
                             elu(acc0.z * inv + bb0.z), elu(acc0.w * inv + bb0.w));
            o1 = make_float4(elu(acc1.x * inv + bb1.x), elu(acc1.y * inv + bb1.y),
                             elu(acc1.z * inv + bb1.z), elu(acc1.w * inv + bb1.w));
        }

        // stage h row in smem, then layer-2 projection for this node
        *(float4*)&sH[w][lane * 8]     = o0;
        *(float4*)&sH[w][lane * 8 + 4] = o1;
        __syncwarp();

        unsigned long long accA = 0ull, accB = 0ull;
        const float4* hr = (const float4*)sH[w];
        #pragma unroll 16
        for (int k4 = 0; k4 < 32; k4++) {
            float4 hx = hr[k4];
            float4 hy = hr[k4 + 32];
            ulonglong2 wpx = sWT[lane][k4];
            ulonglong2 wpy = sWT[lane][k4 + 32];
            fma2(accA, pk2(hx.x, hx.y), wpx.x);
            fma2(accA, pk2(hx.z, hx.w), wpx.y);
            fma2(accB, pk2(hy.x, hy.y), wpy.x);
            fma2(accB, pk2(hy.z, hy.w), wpy.y);
        }
        float peA, poA, peB, poB;
        upk2(accA, peA, poA);
        upk2(accB, peB, poB);
        float f2c = (peA + poA) + (peB + poB);
        g_f2h[(size_t)n * 32 + lane] = __float2half_rn(f2c);
        float pl = f2c * salc, pr = f2c * sarc;
        #pragma unroll
        for (int o = 16; o; o >>= 1) {
            pl += __shfl_xor_sync(0xffffffffu, pl, o);
            pr += __shfl_xor_sync(0xffffffffu, pr, o);
        }
        if (lane == 0) { g_el2[n] = pl; g_er2[n] = pr; }
        __syncwarp();   // all lanes done reading sH before next node overwrites
    }
}

// ---------------- layer-2 aggregation: fp16 f2 gather -> out [N,32] ----------------
__global__ __launch_bounds__(256) void k_agg2(const float* __restrict__ b2, float* __restrict__ out) {
    int warp = (blockIdx.x * blockDim.x + threadIdx.x) >> 5;
    int lane = threadIdx.x & 31;
    if (warp >= NN) return;
    int n = warp;
    int beg = g_offs[n], end = g_offs[n + 1];
    int deg = end - beg;
    float bb = b2[lane];
    if (deg == 0) { out[(size_t)n * 32 + lane] = bb; return; }

    float er_own = g_er2[n];
    float acc = 0.f, wsum = 0.f;

    if (deg <= 32) {
        int myv = (lane < deg) ? __ldg(&g_csr_src[beg + lane]) : 0x7fffffff;
        myv = warp_bitonic32(myv, lane);
        int i = 0;
        for (; i + 4 <= deg; i += 4) {
            int s0 = __shfl_sync(0xffffffffu, myv, i);
            int s1 = __shfl_sync(0xffffffffu, myv, i + 1);
            int s2 = __shfl_sync(0xffffffffu, myv, i + 2);
            int s3 = __shfl_sync(0xffffffffu, myv, i + 3);
            float w0 = __expf(lrelu(__ldg(&g_el2[s0]) + er_own));
            float w1 = __expf(lrelu(__ldg(&g_el2[s1]) + er_own));
            float w2 = __expf(lrelu(__ldg(&g_el2[s2]) + er_own));
            float w3 = __expf(lrelu(__ldg(&g_el2[s3]) + er_own));
            wsum += (w0 + w1) + (w2 + w3);
            float v0 = __half2float(__ldg(&g_f2h[(size_t)s0 * 32 + lane]));
            float v1 = __half2float(__ldg(&g_f2h[(size_t)s1 * 32 + lane]));
            float v2 = __half2float(__ldg(&g_f2h[(size_t)s2 * 32 + lane]));
            float v3 = __half2float(__ldg(&g_f2h[(size_t)s3 * 32 + lane]));
            acc = fmaf(w0, v0, acc);
            acc = fmaf(w1, v1, acc);
            acc = fmaf(w2, v2, acc);
            acc = fmaf(w3, v3, acc);
        }
        for (; i < deg; i++) {
            int s0 = __shfl_sync(0xffffffffu, myv, i);
            float w0 = __expf(lrelu(__ldg(&g_el2[s0]) + er_own));
            wsum += w0;
            acc = fmaf(w0, __half2float(__ldg(&g_f2h[(size_t)s0 * 32 + lane])), acc);
        }
    } else {
        // bucket already sorted in place by k_agg1g2's deg>32 path (deterministic)
        for (int i = beg; i < end; i++) {
            int s0 = __ldg(&g_csr_src[i]);
            float w0 = __expf(lrelu(__ldg(&g_el2[s0]) + er_own));
            wsum += w0;
            acc = fmaf(w0, __half2float(__ldg(&g_f2h[(size_t)s0 * 32 + lane])), acc);
        }
    }
    out[(size_t)n * 32 + lane] = acc / wsum + bb;
}

// ---------------- launch ----------------
extern "C" void kernel_launch(void* const* d_in, const int* in_sizes, int n_in,
                              void* d_out, int out_size) {
    const float* x   = (const float*)d_in[0];
    const int*   src = (const int*)d_in[1];
    const int*   dst = (const int*)d_in[2];
    const float* W1  = (const float*)d_in[3];
    const float* al1 = (const float*)d_in[4];
    const float* ar1 = (const float*)d_in[5];
    const float* b1  = (const float*)d_in[6];
    const float* W2  = (const float*)d_in[7];
    const float* al2 = (const float*)d_in[8];
    const float* ar2 = (const float*)d_in[9];
    const float* b2  = (const float*)d_in[10];
    float* out = (float*)d_out;

    cudaStream_t s2;
    cudaStreamCreateWithFlags(&s2, cudaStreamNonBlocking);
    cudaEvent_t evFork, evCsr, evReset;
    cudaEventCreateWithFlags(&evFork,  cudaEventDisableTiming);
    cudaEventCreateWithFlags(&evCsr,   cudaEventDisableTiming);
    cudaEventCreateWithFlags(&evReset, cudaEventDisableTiming);

    cudaEventRecord(evFork, 0);
    cudaStreamWaitEvent(s2, evFork, 0);

    // branch A (s2): CSR build
    k_degree<<<784, 1024, 0, s2>>>(dst);
    k_scan_lb<<<SCAN_B, 512, 0, s2>>>();
    k_scatter<<<784, 1024, 0, s2>>>(src, dst);
    cudaEventRecord(evCsr, s2);

    // branch B (default stream): layer-1 projection + fused logits
    k_gemm1<<<dim3(2, (NN + 127) / 128), 256>>>(x, W1, al1, ar1);

    // join, then fused agg1+gemm2, then agg2
    cudaStreamWaitEvent(0, evCsr, 0);
    k_agg1g2<<<740, 256>>>(b1, W2, al2, ar2);
    k_reset<<<98, 512, 0, s2>>>();              // overlaps tail on s2
    cudaEventRecord(evReset, s2);
    k_agg2<<<(NN + 7) / 8, 256>>>(b2, out);
    cudaStreamWaitEvent(0, evReset, 0);         // full join for graph capture

    cudaEventDestroy(evFork);
    cudaEventDestroy(evCsr);
    cudaEventDestroy(evReset);
    cudaStreamDestroy(s2);
}

// round 16
// speedup vs baseline: 1.6832x; 1.6832x over previous
#include <cuda_runtime.h>
#include <cuda_fp16.h>
#include <cuda_bf16.h>

#define NN 50000
#define NE 800000
#define SCAN_B 98          // ceil(50000/512)

// ---------------- scratch (device globals; no allocation allowed) ----------------
__device__ __half g_f1h[(size_t)NN * 256]; // layer1 projected features (fp16 storage)
__device__ float g_f2[(size_t)NN * 32];    // layer2 projected features
__device__ float g_el1[NN * 8];
__device__ float g_er1[NN * 8];
__device__ float g_el2[NN];
__device__ float g_er2[NN];
__device__ int   g_offs[NN + 1];
__device__ int   g_cursor[NN];             // zero at call entry (load-time init + tail reset)
__device__ int   g_csr_src[NE];
__device__ unsigned long long g_lb[SCAN_B];// lookback state; zero at call entry

// ---------------- f32x2 packed-FMA helpers ----------------
__device__ __forceinline__ unsigned long long pk2(float x, float y) {
    unsigned long long r;
    asm("mov.b64 %0, {%1, %2};" : "=l"(r) : "f"(x), "f"(y));
    return r;
}
__device__ __forceinline__ void upk2(unsigned long long v, float& x, float& y) {
    asm("mov.b64 {%0, %1}, %2;" : "=f"(x), "=f"(y) : "l"(v));
}
__device__ __forceinline__ void fma2(unsigned long long& c, unsigned long long a, unsigned long long b) {
    asm("fma.rn.f32x2 %0, %1, %2, %0;" : "+l"(c) : "l"(a), "l"(b));
}

__device__ __forceinline__ float lrelu(float e) { return e > 0.f ? e : 0.2f * e; }
__device__ __forceinline__ float elu(float v)   { return v > 0.f ? v : expm1f(v); }

// ascending bitonic sort of 32 values across a warp (pad with INT_MAX)
__device__ __forceinline__ int warp_bitonic32(int v, int lane) {
    #pragma unroll
    for (int k = 2; k <= 32; k <<= 1) {
        #pragma unroll
        for (int j = k >> 1; j > 0; j >>= 1) {
            int other = __shfl_xor_sync(0xffffffffu, v, j);
            bool up = ((lane & k) == 0);
            bool keepMin = (((lane & j) == 0) == up);
            v = keepMin ? min(v, other) : max(v, other);
        }
    }
    return v;
}

// ---------------- CSR build ----------------
__global__ void k_degree(const int* __restrict__ dst) {
    for (int e = blockIdx.x * blockDim.x + threadIdx.x; e < NE; e += gridDim.x * blockDim.x)
        atomicAdd(&g_cursor[dst[e]], 1);
}

// single-pass exclusive scan with decoupled lookback (98 blocks, all resident)
__global__ __launch_bounds__(512) void k_scan_lb() {
    __shared__ int sh[512];
    __shared__ int s_prev;
    int t = threadIdx.x, b = blockIdx.x;
    int i = b * 512 + t;
    int v = (i < NN) ? g_cursor[i] : 0;
    sh[t] = v;
    __syncthreads();
    #pragma unroll
    for (int o = 1; o < 512; o <<= 1) {
        int add = (t >= o) ? sh[t - o] : 0;
        __syncthreads();
        sh[t] += add;
        __syncthreads();
    }
    int total = sh[511];
    if (t < 32) {
        if (b == 0) {
            if (t == 0) {
                atomicExch(&g_lb[0], (2ull << 32) | (unsigned)total);
                s_prev = 0;
            }
        } else {
            if (t == 0) atomicExch(&g_lb[b], (1ull << 32) | (unsigned)total);
            __syncwarp();
            int running = 0;
            int j = b - 1;
            while (true) {
                int idx = j - t;
                unsigned long long s = (idx >= 0) ? atomicAdd(&g_lb[idx], 0ull) : (2ull << 32);
                unsigned f = (unsigned)(s >> 32);
                if (!__all_sync(0xffffffffu, f != 0)) continue;
                unsigned m2 = __ballot_sync(0xffffffffu, f == 2);
                int stop = m2 ? (__ffs(m2) - 1) : 31;
                int contrib = (t <= stop) ? (int)(unsigned)(s & 0xffffffffu) : 0;
                #pragma unroll
                for (int o = 16; o; o >>= 1) contrib += __shfl_xor_sync(0xffffffffu, contrib, o);
                running += contrib;
                if (m2) break;
                j -= 32;
            }
            if (t == 0) {
                atomicExch(&g_lb[b], (2ull << 32) | (unsigned)(running + total));
                s_prev = running;
            }
        }
    }
    __syncthreads();
    int prev = s_prev;
    if (i < NN) {
        int ex = prev + sh[t] - v;
        g_offs[i] = ex;
        g_cursor[i] = ex;
    }
    if (i == NN) g_offs[NN] = NE;
}

__global__ void k_scatter(const int* __restrict__ src, const int* __restrict__ dst) {
    for (int e = blockIdx.x * blockDim.x + threadIdx.x; e < NE; e += gridDim.x * blockDim.x) {
        int p = atomicAdd(&g_cursor[dst[e]], 1);
        g_csr_src[p] = src[e];
    }
}

// tail reset: leaves cursor + lookback state zeroed for the next call
__global__ void k_reset() {
    int i = blockIdx.x * blockDim.x + threadIdx.x;
    if (i < NN) g_cursor[i] = 0;
    if (i < SCAN_B) g_lb[i] = 0ull;
}

// ---------------- GEMM1 + fused logits: f1h = half(X @ W1); el1/er1 fp32 ----------------
__global__ __launch_bounds__(256, 2) void k_gemm1(const float* __restrict__ A, const float* __restrict__ B,
                                                  const float* __restrict__ al1, const float* __restrict__ ar1) {
    __shared__ float As[2][16][132];
    __shared__ float Bs[2][16][128];
    int tid = threadIdx.x;
    int tx = tid & 15, ty = tid >> 4;
    int bn = blockIdx.x * 128;
    int bm = blockIdx.y * 128;

    int arow = tid >> 2, ac4 = tid & 3;
    int arow2 = (tid + 256) >> 2, ac42 = (tid + 256) & 3;
    int bkr = tid >> 5, bc4 = tid & 31;
    int bkr2 = (tid + 256) >> 5, bc42 = (tid + 256) & 31;

    int hA = (bn >> 5) + (tx >> 3);
    int hB = hA + 2;
    int cm = (tx & 7) * 4;
    float4 alA = *(const float4*)(al1 + hA * 32 + cm);
    float4 arA = *(const float4*)(ar1 + hA * 32 + cm);
    float4 alB = *(const float4*)(al1 + hB * 32 + cm);
    float4 arB = *(const float4*)(ar1 + hB * 32 + cm);

    unsigned long long c[8][4];
    #pragma unroll
    for (int i = 0; i < 8; i++)
        #pragma unroll
        for (int j = 0; j < 4; j++) c[i][j] = 0ull;

    float4 ra0, ra1, rb0, rb1;
    {
        int gr0 = bm + arow, gr1 = bm + arow2;
        ra0 = (gr0 < NN) ? *(const float4*)(A + (size_t)gr0 * 128 + ac4 * 4) : make_float4(0.f,0.f,0.f,0.f);
        ra1 = (gr1 < NN) ? *(const float4*)(A + (size_t)gr1 * 128 + ac42 * 4) : make_float4(0.f,0.f,0.f,0.f);
        rb0 = *(const float4*)(B + (size_t)bkr  * 256 + bn + bc4  * 4);
        rb1 = *(const float4*)(B + (size_t)bkr2 * 256 + bn + bc42 * 4);
        As[0][ac4 * 4 + 0][arow] = ra0.x; As[0][ac4 * 4 + 1][arow] = ra0.y;
        As[0][ac4 * 4 + 2][arow] = ra0.z; As[0][ac4 * 4 + 3][arow] = ra0.w;
        As[0][ac42 * 4 + 0][arow2] = ra1.x; As[0][ac42 * 4 + 1][arow2] = ra1.y;
        As[0][ac42 * 4 + 2][arow2] = ra1.z; As[0][ac42 * 4 + 3][arow2] = ra1.w;
        *(float4*)&Bs[0][bkr][bc4 * 4] = rb0;
        *(float4*)&Bs[0][bkr2][bc42 * 4] = rb1;
    }
    __syncthreads();

    #pragma unroll
    for (int t = 0; t < 8; t++) {
        int cur = t & 1;
        if (t < 7) {
            int kt = (t + 1) * 16;
            int gr0 = bm + arow, gr1 = bm + arow2;
            ra0 = (gr0 < NN) ? *(const float4*)(A + (size_t)gr0 * 128 + kt + ac4 * 4) : make_float4(0.f,0.f,0.f,0.f);
            ra1 = (gr1 < NN) ? *(const float4*)(A + (size_t)gr1 * 128 + kt + ac42 * 4) : make_float4(0.f,0.f,0.f,0.f);
            rb0 = *(const float4*)(B + (size_t)(kt + bkr)  * 256 + bn + bc4  * 4);
            rb1 = *(const float4*)(B + (size_t)(kt + bkr2) * 256 + bn + bc42 * 4);
        }
        #pragma unroll
        for (int k = 0; k < 16; k++) {
            float4 a0 = *(const float4*)&As[cur][k][ty * 4];
            float4 a1 = *(const float4*)&As[cur][k][64 + ty * 4];
            float4 b0 = *(const float4*)&Bs[cur][k][tx * 4];
            float4 b1 = *(const float4*)&Bs[cur][k][64 + tx * 4];
            float av[8] = {a0.x, a0.y, a0.z, a0.w, a1.x, a1.y, a1.z, a1.w};
            unsigned long long bp[4];
            bp[0] = pk2(b0.x, b0.y); bp[1] = pk2(b0.z, b0.w);
            bp[2] = pk2(b1.x, b1.y); bp[3] = pk2(b1.z, b1.w);
            #pragma unroll
            for (int i = 0; i < 8; i++) {
                unsigned long long aa = pk2(av[i], av[i]);
                fma2(c[i][0], aa, bp[0]);
                fma2(c[i][1], aa, bp[1]);
                fma2(c[i][2], aa, bp[2]);
                fma2(c[i][3], aa, bp[3]);
            }
        }
        if (t < 7) {
            int nxt = cur ^ 1;
            As[nxt][ac4 * 4 + 0][arow] = ra0.x; As[nxt][ac4 * 4 + 1][arow] = ra0.y;
            As[nxt][ac4 * 4 + 2][arow] = ra0.z; As[nxt][ac4 * 4 + 3][arow] = ra0.w;
            As[nxt][ac42 * 4 + 0][arow2] = ra1.x; As[nxt][ac42 * 4 + 1][arow2] = ra1.y;
            As[nxt][ac42 * 4 + 2][arow2] = ra1.z; As[nxt][ac42 * 4 + 3][arow2] = ra1.w;
            *(float4*)&Bs[nxt][bkr][bc4 * 4] = rb0;
            *(float4*)&Bs[nxt][bkr2][bc42 * 4] = rb1;
        }
        __syncthreads();
    }

    int lane = tid & 31;
    #pragma unroll
    for (int i = 0; i < 8; i++) {
        int mloc = (i < 4) ? (ty * 4 + i) : (64 + ty * 4 + i - 4);
        int gr = bm + mloc;
        float v0, v1, v2, v3, v4, v5, v6, v7;
        upk2(c[i][0], v0, v1); upk2(c[i][1], v2, v3);
        upk2(c[i][2], v4, v5); upk2(c[i][3], v6, v7);
        if (gr < NN) {
            __half2 p0 = __floats2half2_rn(v0, v1);
            __half2 p1 = __floats2half2_rn(v2, v3);
            __half2 p2 = __floats2half2_rn(v4, v5);
            __half2 p3 = __floats2half2_rn(v6, v7);
            uint2 s0 = make_uint2(*(unsigned*)&p0, *(unsigned*)&p1);
            uint2 s1 = make_uint2(*(unsigned*)&p2, *(unsigned*)&p3);
            *(uint2*)(g_f1h + (size_t)gr * 256 + bn + tx * 4)      = s0;
            *(uint2*)(g_f1h + (size_t)gr * 256 + bn + 64 + tx * 4) = s1;
        }
        float elA = v0 * alA.x + v1 * alA.y + v2 * alA.z + v3 * alA.w;
        float erA = v0 * arA.x + v1 * arA.y + v2 * arA.z + v3 * arA.w;
        float elB = v4 * alB.x + v5 * alB.y + v6 * alB.z + v7 * alB.w;
        float erB = v4 * arB.x + v5 * arB.y + v6 * arB.z + v7 * arB.w;
        #pragma unroll
        for (int o = 1; o < 8; o <<= 1) {
            elA += __shfl_xor_sync(0xffffffffu, elA, o);
            erA += __shfl_xor_sync(0xffffffffu, erA, o);
            elB += __shfl_xor_sync(0xffffffffu, elB, o);
            erB += __shfl_xor_sync(0xffffffffu, erB, o);
        }
        if ((lane & 7) == 0 && gr < NN) {
            g_el1[gr * 8 + hA] = elA;  g_er1[gr * 8 + hA] = erA;
            g_el1[gr * 8 + hB] = elB;  g_er1[gr * 8 + hB] = erB;
        }
    }
}

// ---------------- fused layer-1 aggregation + layer-2 projection ----------------
__device__ __forceinline__ void agg1_edge(int s, int lane, int hsel, float er_own,
                                          float4& a0, float4& a1, float& wsum) {
    float w = 0.f;
    if (lane < 8) {
        w = __expf(lrelu(__ldg(&g_el1[s * 8 + lane]) + er_own));
        wsum += w;
    }
    uint4 raw = __ldg((const uint4*)g_f1h + (size_t)s * 32 + lane);
    float wh = __shfl_sync(0xffffffffu, w, hsel);
    __half2 h0 = *(__half2*)&raw.x, h1 = *(__half2*)&raw.y;
    __half2 h2 = *(__half2*)&raw.z, h3 = *(__half2*)&raw.w;
    float2 f0 = __half22float2(h0), f1 = __half22float2(h1);
    float2 f2 = __half22float2(h2), f3 = __half22float2(h3);
    a0.x = fmaf(wh, f0.x, a0.x); a0.y = fmaf(wh, f0.y, a0.y);
    a0.z = fmaf(wh, f1.x, a0.z); a0.w = fmaf(wh, f1.y, a0.w);
    a1.x = fmaf(wh, f2.x, a1.x); a1.y = fmaf(wh, f2.y, a1.y);
    a1.z = fmaf(wh, f3.x, a1.z); a1.w = fmaf(wh, f3.y, a1.w);
}

__global__ __launch_bounds__(256) void k_agg1g2(const float* __restrict__ b1,
                                                const float* __restrict__ W2,
                                                const float* __restrict__ al2,
                                                const float* __restrict__ ar2) {
    __shared__ ulonglong2 sWT[32][65];   // [c][k4] K-packed W2 pairs; pad 65 -> conflict-free
    __shared__ float sH[8][256];         // per-warp h row staging
    __shared__ float sal[32], sar[32];
    int tid = threadIdx.x;
    for (int idx = tid; idx < 2048; idx += 256) {
        int k4 = idx >> 5, cc = idx & 31;
        float w0 = W2[(k4 * 4 + 0) * 32 + cc];
        float w1 = W2[(k4 * 4 + 1) * 32 + cc];
        float w2 = W2[(k4 * 4 + 2) * 32 + cc];
        float w3 = W2[(k4 * 4 + 3) * 32 + cc];
        ulonglong2 p; p.x = pk2(w0, w1); p.y = pk2(w2, w3);
        sWT[cc][k4] = p;
    }
    if (tid < 32) { sal[tid] = al2[tid]; sar[tid] = ar2[tid]; }
    __syncthreads();

    int lane = tid & 31;
    int w = tid >> 5;
    int gwarp = (blockIdx.x * blockDim.x + tid) >> 5;
    int nwarps = (gridDim.x * blockDim.x) >> 5;
    float4 bb0 = *(const float4*)(b1 + lane * 8);
    float4 bb1 = *(const float4*)(b1 + lane * 8 + 4);
    int hsel = lane >> 2;
    float salc = sal[lane], sarc = sar[lane];

    for (int n = gwarp; n < NN; n += nwarps) {
        int beg = g_offs[n], end = g_offs[n + 1];
        int deg = end - beg;
        float4 o0, o1;

        if (deg == 0) {
            o0 = make_float4(elu(bb0.x), elu(bb0.y), elu(bb0.z), elu(bb0.w));
            o1 = make_float4(elu(bb1.x), elu(bb1.y), elu(bb1.z), elu(bb1.w));
        } else {
            float er_own = (lane < 8) ? g_er1[n * 8 + lane] : 0.f;
            float4 acc0 = make_float4(0.f, 0.f, 0.f, 0.f);
            float4 acc1 = make_float4(0.f, 0.f, 0.f, 0.f);
            float wsum = 0.f;

            if (deg <= 32) {
                int myv = (lane < deg) ? __ldg(&g_csr_src[beg + lane]) : 0x7fffffff;
                myv = warp_bitonic32(myv, lane);
                int i = 0;
                for (; i + 4 <= deg; i += 4) {
                    int s0 = __shfl_sync(0xffffffffu, myv, i);
                    int s1 = __shfl_sync(0xffffffffu, myv, i + 1);
                    int s2 = __shfl_sync(0xffffffffu, myv, i + 2);
                    int s3 = __shfl_sync(0xffffffffu, myv, i + 3);
                    agg1_edge(s0, lane, hsel, er_own, acc0, acc1, wsum);
                    agg1_edge(s1, lane, hsel, er_own, acc0, acc1, wsum);
                    agg1_edge(s2, lane, hsel, er_own, acc0, acc1, wsum);
                    agg1_edge(s3, lane, hsel, er_own, acc0, acc1, wsum);
                }
                for (; i < deg; i++) {
                    int s0 = __shfl_sync(0xffffffffu, myv, i);
                    agg1_edge(s0, lane, hsel, er_own, acc0, acc1, wsum);
                }
            } else {
                if (lane == 0) {   // rare: deterministic in-place global insertion sort
                    for (int i = beg + 1; i < end; i++) {
                        int key = g_csr_src[i];
                        int j = i - 1;
                        while (j >= beg && g_csr_src[j] > key) { g_csr_src[j + 1] = g_csr_src[j]; j--; }
                        g_csr_src[j + 1] = key;
                    }
                }
                __syncwarp();
                for (int i = beg; i < end; i++) {
                    int s0 = g_csr_src[i];
                    agg1_edge(s0, lane, hsel, er_own, acc0, acc1, wsum);
                }
            }

            float d = __shfl_sync(0xffffffffu, wsum, hsel);
            float inv = 1.f / d;
            o0 = make_float4(elu(acc0.x * inv + bb0.x), elu(acc0.y * inv + bb0.y),
                             elu(acc0.z * inv + bb0.z), elu(acc0.w * inv + bb0.w));
            o1 = make_float4(elu(acc1.x * inv + bb1.x), elu(acc1.y * inv + bb1.y),
                             elu(acc1.z * inv + bb1.z), elu(acc1.w * inv + bb1.w));
        }

        // stage h row in smem, then layer-2 projection for this node
        *(float4*)&sH[w][lane * 8]     = o0;
        *(float4*)&sH[w][lane * 8 + 4] = o1;
        __syncwarp();

        unsigned long long acc = 0ull;
        const float4* hr = (const float4*)sH[w];
        #pragma unroll 16
        for (int k4 = 0; k4 < 64; k4++) {
            float4 h = hr[k4];                  // broadcast LDS.128
            ulonglong2 wp = sWT[lane][k4];      // conflict-free LDS.128
            fma2(acc, pk2(h.x, h.y), wp.x);
            fma2(acc, pk2(h.z, h.w), wp.y);
        }
        float pe, po;
        upk2(acc, pe, po);
        float f2c = pe + po;
        g_f2[(size_t)n * 32 + lane] = f2c;
        float pl = f2c * salc, pr = f2c * sarc;
        #pragma unroll
        for (int o = 16; o; o >>= 1) {
            pl += __shfl_xor_sync(0xffffffffu, pl, o);
            pr += __shfl_xor_sync(0xffffffffu, pr, o);
        }
        if (lane == 0) { g_el2[n] = pl; g_er2[n] = pr; }
        __syncwarp();   // all lanes done reading sH before next node overwrites
    }
}

// ---------------- layer-2 aggregation: in-register bucket sort -> out [N,32] ----------------
__global__ __launch_bounds__(256) void k_agg2(const float* __restrict__ b2, float* __restrict__ out) {
    int warp = (blockIdx.x * blockDim.x + threadIdx.x) >> 5;
    int lane = threadIdx.x & 31;
    if (warp >= NN) return;
    int n = warp;
    int beg = g_offs[n], end = g_offs[n + 1];
    int deg = end - beg;
    float bb = b2[lane];
    if (deg == 0) { out[(size_t)n * 32 + lane] = bb; return; }

    float er_own = g_er2[n];
    float acc = 0.f, wsum = 0.f;

    if (deg <= 32) {
        int myv = (lane < deg) ? __ldg(&g_csr_src[beg + lane]) : 0x7fffffff;
        myv = warp_bitonic32(myv, lane);
        int i = 0;
        for (; i + 4 <= deg; i += 4) {
            int s0 = __shfl_sync(0xffffffffu, myv, i);
            int s1 = __shfl_sync(0xffffffffu, myv, i + 1);
            int s2 = __shfl_sync(0xffffffffu, myv, i + 2);
            int s3 = __shfl_sync(0xffffffffu, myv, i + 3);
            float w0 = __expf(lrelu(__ldg(&g_el2[s0]) + er_own));
            float w1 = __expf(lrelu(__ldg(&g_el2[s1]) + er_own));
            float w2 = __expf(lrelu(__ldg(&g_el2[s2]) + er_own));
            float w3 = __expf(lrelu(__ldg(&g_el2[s3]) + er_own));
            wsum += (w0 + w1) + (w2 + w3);
            float v0 = __ldg(&g_f2[(size_t)s0 * 32 + lane]);
            float v1 = __ldg(&g_f2[(size_t)s1 * 32 + lane]);
            float v2 = __ldg(&g_f2[(size_t)s2 * 32 + lane]);
            float v3 = __ldg(&g_f2[(size_t)s3 * 32 + lane]);
            acc = fmaf(w0, v0, acc);
            acc = fmaf(w1, v1, acc);
            acc = fmaf(w2, v2, acc);
            acc = fmaf(w3, v3, acc);
        }
        for (; i < deg; i++) {
            int s0 = __shfl_sync(0xffffffffu, myv, i);
            float w0 = __expf(lrelu(__ldg(&g_el2[s0]) + er_own));
            wsum += w0;
            acc = fmaf(w0, __ldg(&g_f2[(size_t)s0 * 32 + lane]), acc);
        }
    } else {
        // bucket already sorted in place by k_agg1g2's deg>32 path (deterministic)
        for (int i = beg; i < end; i++) {
            int s0 = __ldg(&g_csr_src[i]);
            float w0 = __expf(lrelu(__ldg(&g_el2[s0]) + er_own));
            wsum += w0;
            acc = fmaf(w0, __ldg(&g_f2[(size_t)s0 * 32 + lane]), acc);
        }
    }
    out[(size_t)n * 32 + lane] = acc / wsum + bb;
}

// ---------------- launch ----------------
extern "C" void kernel_launch(void* const* d_in, const int* in_sizes, int n_in,
                              void* d_out, int out_size) {
    const float* x   = (const float*)d_in[0];
    const int*   src = (const int*)d_in[1];
    const int*   dst = (const int*)d_in[2];
    const float* W1  = (const float*)d_in[3];
    const float* al1 = (const float*)d_in[4];
    const float* ar1 = (const float*)d_in[5];
    const float* b1  = (const float*)d_in[6];
    const float* W2  = (const float*)d_in[7];
    const float* al2 = (const float*)d_in[8];
    const float* ar2 = (const float*)d_in[9];
    const float* b2  = (const float*)d_in[10];
    float* out = (float*)d_out;

    cudaStream_t s2;
    cudaStreamCreateWithFlags(&s2, cudaStreamNonBlocking);
    cudaEvent_t evFork, evCsr, evReset;
    cudaEventCreateWithFlags(&evFork,  cudaEventDisableTiming);
    cudaEventCreateWithFlags(&evCsr,   cudaEventDisableTiming);
    cudaEventCreateWithFlags(&evReset, cudaEventDisableTiming);

    cudaEventRecord(evFork, 0);
    cudaStreamWaitEvent(s2, evFork, 0);

    // branch A (s2): CSR build
    k_degree<<<784, 1024, 0, s2>>>(dst);
    k_scan_lb<<<SCAN_B, 512, 0, s2>>>();
    k_scatter<<<784, 1024, 0, s2>>>(src, dst);
    cudaEventRecord(evCsr, s2);

    // branch B (default stream): layer-1 projection + fused logits
    k_gemm1<<<dim3(2, (NN + 127) / 128), 256>>>(x, W1, al1, ar1);

    // join, then fused agg1+gemm2, then agg2
    cudaStreamWaitEvent(0, evCsr, 0);
    k_agg1g2<<<740, 256>>>(b1, W2, al2, ar2);
    k_reset<<<98, 512, 0, s2>>>();              // overlaps tail on s2
    cudaEventRecord(evReset, s2);
    k_agg2<<<(NN + 7) / 8, 256>>>(b2, out);
    cudaStreamWaitEvent(0, evReset, 0);         // full join for graph capture

    cudaEventDestroy(evFork);
    cudaEventDestroy(evCsr);
    cudaEventDestroy(evReset);
    cudaStreamDestroy(s2);
}

// round 17
// speedup vs baseline: 1.9120x; 1.1360x over previous
#include <cuda_runtime.h>
#include <cuda_fp16.h>
#include <cuda_bf16.h>

#define NN 50000
#define NE 800000
#define SCAN_B 98          // ceil(50000/512)

// ---------------- scratch (device globals; no allocation allowed) ----------------
__device__ __half g_f1h[(size_t)NN * 256]; // layer1 projected features (fp16 storage)
__device__ float g_f2[(size_t)NN * 32];    // layer2 projected features
__device__ float g_el1[NN * 8];
__device__ float g_er1[NN * 8];
__device__ float g_el2[NN];
__device__ float g_er2[NN];
__device__ int   g_offs[NN + 1];
__device__ int   g_cursor[NN];             // zero at call entry (load-time init + tail reset)
__device__ int   g_csr_src[NE];
__device__ unsigned long long g_lb[SCAN_B];// lookback state; zero at call entry

// ---------------- f32x2 packed-FMA helpers ----------------
__device__ __forceinline__ unsigned long long pk2(float x, float y) {
    unsigned long long r;
    asm("mov.b64 %0, {%1, %2};" : "=l"(r) : "f"(x), "f"(y));
    return r;
}
__device__ __forceinline__ void upk2(unsigned long long v, float& x, float& y) {
    asm("mov.b64 {%0, %1}, %2;" : "=f"(x), "=f"(y) : "l"(v));
}
__device__ __forceinline__ void fma2(unsigned long long& c, unsigned long long a, unsigned long long b) {
    asm("fma.rn.f32x2 %0, %1, %2, %0;" : "+l"(c) : "l"(a), "l"(b));
}

__device__ __forceinline__ float lrelu(float e) { return e > 0.f ? e : 0.2f * e; }
__device__ __forceinline__ float elu(float v)   { return v > 0.f ? v : expm1f(v); }

// ascending bitonic sort of 32 values across a warp (pad with INT_MAX)
__device__ __forceinline__ int warp_bitonic32(int v, int lane) {
    #pragma unroll
    for (int k = 2; k <= 32; k <<= 1) {
        #pragma unroll
        for (int j = k >> 1; j > 0; j >>= 1) {
            int other = __shfl_xor_sync(0xffffffffu, v, j);
            bool up = ((lane & k) == 0);
            bool keepMin = (((lane & j) == 0) == up);
            v = keepMin ? min(v, other) : max(v, other);
        }
    }
    return v;
}

// ---------------- CSR build ----------------
__global__ void k_degree(const int* __restrict__ dst) {
    for (int e = blockIdx.x * blockDim.x + threadIdx.x; e < NE; e += gridDim.x * blockDim.x)
        atomicAdd(&g_cursor[dst[e]], 1);
}

// single-pass exclusive scan with decoupled lookback (98 blocks, all resident)
__global__ __launch_bounds__(512) void k_scan_lb() {
    __shared__ int sh[512];
    __shared__ int s_prev;
    int t = threadIdx.x, b = blockIdx.x;
    int i = b * 512 + t;
    int v = (i < NN) ? g_cursor[i] : 0;
    sh[t] = v;
    __syncthreads();
    #pragma unroll
    for (int o = 1; o < 512; o <<= 1) {
        int add = (t >= o) ? sh[t - o] : 0;
        __syncthreads();
        sh[t] += add;
        __syncthreads();
    }
    int total = sh[511];
    if (t < 32) {
        if (b == 0) {
            if (t == 0) {
                atomicExch(&g_lb[0], (2ull << 32) | (unsigned)total);
                s_prev = 0;
            }
        } else {
            if (t == 0) atomicExch(&g_lb[b], (1ull << 32) | (unsigned)total);
            __syncwarp();
            int running = 0;
            int j = b - 1;
            while (true) {
                int idx = j - t;
                unsigned long long s = (idx >= 0) ? atomicAdd(&g_lb[idx], 0ull) : (2ull << 32);
                unsigned f = (unsigned)(s >> 32);
                if (!__all_sync(0xffffffffu, f != 0)) continue;
                unsigned m2 = __ballot_sync(0xffffffffu, f == 2);
                int stop = m2 ? (__ffs(m2) - 1) : 31;
                int contrib = (t <= stop) ? (int)(unsigned)(s & 0xffffffffu) : 0;
                #pragma unroll
                for (int o = 16; o; o >>= 1) contrib += __shfl_xor_sync(0xffffffffu, contrib, o);
                running += contrib;
                if (m2) break;
                j -= 32;
            }
            if (t == 0) {
                atomicExch(&g_lb[b], (2ull << 32) | (unsigned)(running + total));
                s_prev = running;
            }
        }
    }
    __syncthreads();
    int prev = s_prev;
    if (i < NN) {
        int ex = prev + sh[t] - v;
        g_offs[i] = ex;
        g_cursor[i] = ex;
    }
    if (i == NN) g_offs[NN] = NE;
}

__global__ void k_scatter(const int* __restrict__ src, const int* __restrict__ dst) {
    for (int e = blockIdx.x * blockDim.x + threadIdx.x; e < NE; e += gridDim.x * blockDim.x) {
        int p = atomicAdd(&g_cursor[dst[e]], 1);
        g_csr_src[p] = src[e];
    }
}

// tail reset: leaves cursor + lookback state zeroed for the next call
__global__ void k_reset() {
    int i = blockIdx.x * blockDim.x + threadIdx.x;
    if (i < NN) g_cursor[i] = 0;
    if (i < SCAN_B) g_lb[i] = 0ull;
}

// ---------------- GEMM1 + fused logits: f1h = half(X @ W1); el1/er1 fp32 ----------------
__global__ __launch_bounds__(256, 2) void k_gemm1(const float* __restrict__ A, const float* __restrict__ B,
                                                  const float* __restrict__ al1, const float* __restrict__ ar1) {
    __shared__ float As[2][16][132];
    __shared__ float Bs[2][16][128];
    int tid = threadIdx.x;
    int tx = tid & 15, ty = tid >> 4;
    int bn = blockIdx.x * 128;
    int bm = blockIdx.y * 128;

    int arow = tid >> 2, ac4 = tid & 3;
    int arow2 = (tid + 256) >> 2, ac42 = (tid + 256) & 3;
    int bkr = tid >> 5, bc4 = tid & 31;
    int bkr2 = (tid + 256) >> 5, bc42 = (tid + 256) & 31;

    int hA = (bn >> 5) + (tx >> 3);
    int hB = hA + 2;
    int cm = (tx & 7) * 4;
    float4 alA = *(const float4*)(al1 + hA * 32 + cm);
    float4 arA = *(const float4*)(ar1 + hA * 32 + cm);
    float4 alB = *(const float4*)(al1 + hB * 32 + cm);
    float4 arB = *(const float4*)(ar1 + hB * 32 + cm);

    unsigned long long c[8][4];
    #pragma unroll
    for (int i = 0; i < 8; i++)
        #pragma unroll
        for (int j = 0; j < 4; j++) c[i][j] = 0ull;

    float4 ra0, ra1, rb0, rb1;
    {
        int gr0 = bm + arow, gr1 = bm + arow2;
        ra0 = (gr0 < NN) ? *(const float4*)(A + (size_t)gr0 * 128 + ac4 * 4) : make_float4(0.f,0.f,0.f,0.f);
        ra1 = (gr1 < NN) ? *(const float4*)(A + (size_t)gr1 * 128 + ac42 * 4) : make_float4(0.f,0.f,0.f,0.f);
        rb0 = *(const float4*)(B + (size_t)bkr  * 256 + bn + bc4  * 4);
        rb1 = *(const float4*)(B + (size_t)bkr2 * 256 + bn + bc42 * 4);
        As[0][ac4 * 4 + 0][arow] = ra0.x; As[0][ac4 * 4 + 1][arow] = ra0.y;
        As[0][ac4 * 4 + 2][arow] = ra0.z; As[0][ac4 * 4 + 3][arow] = ra0.w;
        As[0][ac42 * 4 + 0][arow2] = ra1.x; As[0][ac42 * 4 + 1][arow2] = ra1.y;
        As[0][ac42 * 4 + 2][arow2] = ra1.z; As[0][ac42 * 4 + 3][arow2] = ra1.w;
        *(float4*)&Bs[0][bkr][bc4 * 4] = rb0;
        *(float4*)&Bs[0][bkr2][bc42 * 4] = rb1;
    }
    __syncthreads();

    #pragma unroll
    for (int t = 0; t < 8; t++) {
        int cur = t & 1;
        if (t < 7) {
            int kt = (t + 1) * 16;
            int gr0 = bm + arow, gr1 = bm + arow2;
            ra0 = (gr0 < NN) ? *(const float4*)(A + (size_t)gr0 * 128 + kt + ac4 * 4) : make_float4(0.f,0.f,0.f,0.f);
            ra1 = (gr1 < NN) ? *(const float4*)(A + (size_t)gr1 * 128 + kt + ac42 * 4) : make_float4(0.f,0.f,0.f,0.f);
            rb0 = *(const float4*)(B + (size_t)(kt + bkr)  * 256 + bn + bc4  * 4);
            rb1 = *(const float4*)(B + (size_t)(kt + bkr2) * 256 + bn + bc42 * 4);
        }
        #pragma unroll
        for (int k = 0; k < 16; k++) {
            float4 a0 = *(const float4*)&As[cur][k][ty * 4];
            float4 a1 = *(const float4*)&As[cur][k][64 + ty * 4];
            float4 b0 = *(const float4*)&Bs[cur][k][tx * 4];
            float4 b1 = *(const float4*)&Bs[cur][k][64 + tx * 4];
            float av[8] = {a0.x, a0.y, a0.z, a0.w, a1.x, a1.y, a1.z, a1.w};
            unsigned long long bp[4];
            bp[0] = pk2(b0.x, b0.y); bp[1] = pk2(b0.z, b0.w);
            bp[2] = pk2(b1.x, b1.y); bp[3] = pk2(b1.z, b1.w);
            #pragma unroll
            for (int i = 0; i < 8; i++) {
                unsigned long long aa = pk2(av[i], av[i]);
                fma2(c[i][0], aa, bp[0]);
                fma2(c[i][1], aa, bp[1]);
                fma2(c[i][2], aa, bp[2]);
                fma2(c[i][3], aa, bp[3]);
            }
        }
        if (t < 7) {
            int nxt = cur ^ 1;
            As[nxt][ac4 * 4 + 0][arow] = ra0.x; As[nxt][ac4 * 4 + 1][arow] = ra0.y;
            As[nxt][ac4 * 4 + 2][arow] = ra0.z; As[nxt][ac4 * 4 + 3][arow] = ra0.w;
            As[nxt][ac42 * 4 + 0][arow2] = ra1.x; As[nxt][ac42 * 4 + 1][arow2] = ra1.y;
            As[nxt][ac42 * 4 + 2][arow2] = ra1.z; As[nxt][ac42 * 4 + 3][arow2] = ra1.w;
            *(float4*)&Bs[nxt][bkr][bc4 * 4] = rb0;
            *(float4*)&Bs[nxt][bkr2][bc42 * 4] = rb1;
        }
        __syncthreads();
    }

    int lane = tid & 31;
    #pragma unroll
    for (int i = 0; i < 8; i++) {
        int mloc = (i < 4) ? (ty * 4 + i) : (64 + ty * 4 + i - 4);
        int gr = bm + mloc;
        float v0, v1, v2, v3, v4, v5, v6, v7;
        upk2(c[i][0], v0, v1); upk2(c[i][1], v2, v3);
        upk2(c[i][2], v4, v5); upk2(c[i][3], v6, v7);
        if (gr < NN) {
            __half2 p0 = __floats2half2_rn(v0, v1);
            __half2 p1 = __floats2half2_rn(v2, v3);
            __half2 p2 = __floats2half2_rn(v4, v5);
            __half2 p3 = __floats2half2_rn(v6, v7);
            uint2 s0 = make_uint2(*(unsigned*)&p0, *(unsigned*)&p1);
            uint2 s1 = make_uint2(*(unsigned*)&p2, *(unsigned*)&p3);
            *(uint2*)(g_f1h + (size_t)gr * 256 + bn + tx * 4)      = s0;
            *(uint2*)(g_f1h + (size_t)gr * 256 + bn + 64 + tx * 4) = s1;
        }
        float elA = v0 * alA.x + v1 * alA.y + v2 * alA.z + v3 * alA.w;
        float erA = v0 * arA.x + v1 * arA.y + v2 * arA.z + v3 * arA.w;
        float elB = v4 * alB.x + v5 * alB.y + v6 * alB.z + v7 * alB.w;
        float erB = v4 * arB.x + v5 * arB.y + v6 * arB.z + v7 * arB.w;
        #pragma unroll
        for (int o = 1; o < 8; o <<= 1) {
            elA += __shfl_xor_sync(0xffffffffu, elA, o);
            erA += __shfl_xor_sync(0xffffffffu, erA, o);
            elB += __shfl_xor_sync(0xffffffffu, elB, o);
            erB += __shfl_xor_sync(0xffffffffu, erB, o);
        }
        if ((lane & 7) == 0 && gr < NN) {
            g_el1[gr * 8 + hA] = elA;  g_er1[gr * 8 + hA] = erA;
            g_el1[gr * 8 + hB] = elB;  g_er1[gr * 8 + hB] = erB;
        }
    }
}

// ---------------- fused layer-1 aggregation + layer-2 projection ----------------
__device__ __forceinline__ void agg1_edge(int s, int lane, int hsel, float er_own,
                                          float4& a0, float4& a1, float& wsum) {
    float w = 0.f;
    if (lane < 8) {
        w = __expf(lrelu(__ldg(&g_el1[s * 8 + lane]) + er_own));
        wsum += w;
    }
    uint4 raw = __ldg((const uint4*)g_f1h + (size_t)s * 32 + lane);
    float wh = __shfl_sync(0xffffffffu, w, hsel);
    __half2 h0 = *(__half2*)&raw.x, h1 = *(__half2*)&raw.y;
    __half2 h2 = *(__half2*)&raw.z, h3 = *(__half2*)&raw.w;
    float2 f0 = __half22float2(h0), f1 = __half22float2(h1);
    float2 f2 = __half22float2(h2), f3 = __half22float2(h3);
    a0.x = fmaf(wh, f0.x, a0.x); a0.y = fmaf(wh, f0.y, a0.y);
    a0.z = fmaf(wh, f1.x, a0.z); a0.w = fmaf(wh, f1.y, a0.w);
    a1.x = fmaf(wh, f2.x, a1.x); a1.y = fmaf(wh, f2.y, a1.y);
    a1.z = fmaf(wh, f3.x, a1.z); a1.w = fmaf(wh, f3.y, a1.w);
}

__global__ __launch_bounds__(256, 6) void k_agg1g2(const float* __restrict__ b1,
                                                   const float* __restrict__ W2,
                                                   const float* __restrict__ al2,
                                                   const float* __restrict__ ar2) {
    __shared__ uint4 sWTh[32][33];       // [c][k8]: 8 fp16 weights W2[k8*8+j][c]; odd stride -> conflict-free
    __shared__ float sH[8][256];         // per-warp h row staging
    __shared__ float sal[32], sar[32];
    int tid = threadIdx.x;
    for (int idx = tid; idx < 1024; idx += 256) {
        int k8 = idx >> 5, cc = idx & 31;
        __half2 a = __floats2half2_rn(W2[(k8 * 8 + 0) * 32 + cc], W2[(k8 * 8 + 1) * 32 + cc]);
        __half2 b = __floats2half2_rn(W2[(k8 * 8 + 2) * 32 + cc], W2[(k8 * 8 + 3) * 32 + cc]);
        __half2 c2 = __floats2half2_rn(W2[(k8 * 8 + 4) * 32 + cc], W2[(k8 * 8 + 5) * 32 + cc]);
        __half2 d = __floats2half2_rn(W2[(k8 * 8 + 6) * 32 + cc], W2[(k8 * 8 + 7) * 32 + cc]);
        uint4 v;
        v.x = *(unsigned*)&a;  v.y = *(unsigned*)&b;
        v.z = *(unsigned*)&c2; v.w = *(unsigned*)&d;
        sWTh[cc][k8] = v;
    }
    if (tid < 32) { sal[tid] = al2[tid]; sar[tid] = ar2[tid]; }
    __syncthreads();

    int lane = tid & 31;
    int w = tid >> 5;
    int gwarp = (blockIdx.x * blockDim.x + tid) >> 5;
    int nwarps = (gridDim.x * blockDim.x) >> 5;
    float4 bb0 = *(const float4*)(b1 + lane * 8);
    float4 bb1 = *(const float4*)(b1 + lane * 8 + 4);
    int hsel = lane >> 2;
    float salc = sal[lane], sarc = sar[lane];

    for (int n = gwarp; n < NN; n += nwarps) {
        int beg = g_offs[n], end = g_offs[n + 1];
        int deg = end - beg;
        float4 o0, o1;

        if (deg == 0) {
            o0 = make_float4(elu(bb0.x), elu(bb0.y), elu(bb0.z), elu(bb0.w));
            o1 = make_float4(elu(bb1.x), elu(bb1.y), elu(bb1.z), elu(bb1.w));
        } else {
            float er_own = (lane < 8) ? g_er1[n * 8 + lane] : 0.f;
            float4 acc0 = make_float4(0.f, 0.f, 0.f, 0.f);
            float4 acc1 = make_float4(0.f, 0.f, 0.f, 0.f);
            float wsum = 0.f;

            if (deg <= 32) {
                int myv = (lane < deg) ? __ldg(&g_csr_src[beg + lane]) : 0x7fffffff;
                myv = warp_bitonic32(myv, lane);
                int i = 0;
                for (; i + 4 <= deg; i += 4) {
                    int s0 = __shfl_sync(0xffffffffu, myv, i);
                    int s1 = __shfl_sync(0xffffffffu, myv, i + 1);
                    int s2 = __shfl_sync(0xffffffffu, myv, i + 2);
                    int s3 = __shfl_sync(0xffffffffu, myv, i + 3);
                    agg1_edge(s0, lane, hsel, er_own, acc0, acc1, wsum);
                    agg1_edge(s1, lane, hsel, er_own, acc0, acc1, wsum);
                    agg1_edge(s2, lane, hsel, er_own, acc0, acc1, wsum);
                    agg1_edge(s3, lane, hsel, er_own, acc0, acc1, wsum);
                }
                for (; i < deg; i++) {
                    int s0 = __shfl_sync(0xffffffffu, myv, i);
                    agg1_edge(s0, lane, hsel, er_own, acc0, acc1, wsum);
                }
            } else {
                if (lane == 0) {   // rare: deterministic in-place global insertion sort
                    for (int i = beg + 1; i < end; i++) {
                        int key = g_csr_src[i];
                        int j = i - 1;
                        while (j >= beg && g_csr_src[j] > key) { g_csr_src[j + 1] = g_csr_src[j]; j--; }
                        g_csr_src[j + 1] = key;
                    }
                }
                __syncwarp();
                for (int i = beg; i < end; i++) {
                    int s0 = g_csr_src[i];
                    agg1_edge(s0, lane, hsel, er_own, acc0, acc1, wsum);
                }
            }

            float d = __shfl_sync(0xffffffffu, wsum, hsel);
            float inv = 1.f / d;
            o0 = make_float4(elu(acc0.x * inv + bb0.x), elu(acc0.y * inv + bb0.y),
                             elu(acc0.z * inv + bb0.z), elu(acc0.w * inv + bb0.w));
            o1 = make_float4(elu(acc1.x * inv + bb1.x), elu(acc1.y * inv + bb1.y),
                             elu(acc1.z * inv + bb1.z), elu(acc1.w * inv + bb1.w));
        }

        // stage h row in smem, then layer-2 projection for this node
        *(float4*)&sH[w][lane * 8]     = o0;
        *(float4*)&sH[w][lane * 8 + 4] = o1;
        __syncwarp();

        float accA = 0.f, accB = 0.f;
        const float4* hr = (const float4*)sH[w];
        #pragma unroll 8
        for (int k8 = 0; k8 < 32; k8++) {
            float4 ha = hr[2 * k8];
            float4 hb = hr[2 * k8 + 1];
            uint4 wp = sWTh[lane][k8];
            float2 w0 = __half22float2(*(__half2*)&wp.x);
            float2 w1 = __half22float2(*(__half2*)&wp.y);
            float2 w2 = __half22float2(*(__half2*)&wp.z);
            float2 w3 = __half22float2(*(__half2*)&wp.w);
            accA = fmaf(ha.x, w0.x, accA); accA = fmaf(ha.y, w0.y, accA);
            accA = fmaf(ha.z, w1.x, accA); accA = fmaf(ha.w, w1.y, accA);
            accB = fmaf(hb.x, w2.x, accB); accB = fmaf(hb.y, w2.y, accB);
            accB = fmaf(hb.z, w3.x, accB); accB = fmaf(hb.w, w3.y, accB);
        }
        float f2c = accA + accB;
        g_f2[(size_t)n * 32 + lane] = f2c;
        float pl = f2c * salc, pr = f2c * sarc;
        #pragma unroll
        for (int o = 16; o; o >>= 1) {
            pl += __shfl_xor_sync(0xffffffffu, pl, o);
            pr += __shfl_xor_sync(0xffffffffu, pr, o);
        }
        if (lane == 0) { g_el2[n] = pl; g_er2[n] = pr; }
        __syncwarp();   // all lanes done reading sH before next node overwrites
    }
}

// ---------------- layer-2 aggregation: in-register bucket sort -> out [N,32] ----------------
__global__ __launch_bounds__(256) void k_agg2(const float* __restrict__ b2, float* __restrict__ out) {
    int warp = (blockIdx.x * blockDim.x + threadIdx.x) >> 5;
    int lane = threadIdx.x & 31;
    if (warp >= NN) return;
    int n = warp;
    int beg = g_offs[n], end = g_offs[n + 1];
    int deg = end - beg;
    float bb = b2[lane];
    if (deg == 0) { out[(size_t)n * 32 + lane] = bb; return; }

    float er_own = g_er2[n];
    float acc = 0.f, wsum = 0.f;

    if (deg <= 32) {
        int myv = (lane < deg) ? __ldg(&g_csr_src[beg + lane]) : 0x7fffffff;
        myv = warp_bitonic32(myv, lane);
        int i = 0;
        for (; i + 4 <= deg; i += 4) {
            int s0 = __shfl_sync(0xffffffffu, myv, i);
            int s1 = __shfl_sync(0xffffffffu, myv, i + 1);
            int s2 = __shfl_sync(0xffffffffu, myv, i + 2);
            int s3 = __shfl_sync(0xffffffffu, myv, i + 3);
            float w0 = __expf(lrelu(__ldg(&g_el2[s0]) + er_own));
            float w1 = __expf(lrelu(__ldg(&g_el2[s1]) + er_own));
            float w2 = __expf(lrelu(__ldg(&g_el2[s2]) + er_own));
            float w3 = __expf(lrelu(__ldg(&g_el2[s3]) + er_own));
            wsum += (w0 + w1) + (w2 + w3);
            float v0 = __ldg(&g_f2[(size_t)s0 * 32 + lane]);
            float v1 = __ldg(&g_f2[(size_t)s1 * 32 + lane]);
            float v2 = __ldg(&g_f2[(size_t)s2 * 32 + lane]);
            float v3 = __ldg(&g_f2[(size_t)s3 * 32 + lane]);
            acc = fmaf(w0, v0, acc);
            acc = fmaf(w1, v1, acc);
            acc = fmaf(w2, v2, acc);
            acc = fmaf(w3, v3, acc);
        }
        for (; i < deg; i++) {
            int s0 = __shfl_sync(0xffffffffu, myv, i);
            float w0 = __expf(lrelu(__ldg(&g_el2[s0]) + er_own));
            wsum += w0;
            acc = fmaf(w0, __ldg(&g_f2[(size_t)s0 * 32 + lane]), acc);
        }
    } else {
        // bucket already sorted in place by k_agg1g2's deg>32 path (deterministic)
        for (int i = beg; i < end; i++) {
            int s0 = __ldg(&g_csr_src[i]);
            float w0 = __expf(lrelu(__ldg(&g_el2[s0]) + er_own));
            wsum += w0;
            acc = fmaf(w0, __ldg(&g_f2[(size_t)s0 * 32 + lane]), acc);
        }
    }
    out[(size_t)n * 32 + lane] = acc / wsum + bb;
}

// ---------------- launch ----------------
extern "C" void kernel_launch(void* const* d_in, const int* in_sizes, int n_in,
                              void* d_out, int out_size) {
    const float* x   = (const float*)d_in[0];
    const int*   src = (const int*)d_in[1];
    const int*   dst = (const int*)d_in[2];
    const float* W1  = (const float*)d_in[3];
    const float* al1 = (const float*)d_in[4];
    const float* ar1 = (const float*)d_in[5];
    const float* b1  = (const float*)d_in[6];
    const float* W2  = (const float*)d_in[7];
    const float* al2 = (const float*)d_in[8];
    const float* ar2 = (const float*)d_in[9];
    const float* b2  = (const float*)d_in[10];
    float* out = (float*)d_out;

    cudaStream_t s2;
    cudaStreamCreateWithFlags(&s2, cudaStreamNonBlocking);
    cudaEvent_t evFork, evCsr, evReset;
    cudaEventCreateWithFlags(&evFork,  cudaEventDisableTiming);
    cudaEventCreateWithFlags(&evCsr,   cudaEventDisableTiming);
    cudaEventCreateWithFlags(&evReset, cudaEventDisableTiming);

    cudaEventRecord(evFork, 0);
    cudaStreamWaitEvent(s2, evFork, 0);

    // branch A (s2): CSR build
    k_degree<<<784, 1024, 0, s2>>>(dst);
    k_scan_lb<<<SCAN_B, 512, 0, s2>>>();
    k_scatter<<<784, 1024, 0, s2>>>(src, dst);
    cudaEventRecord(evCsr, s2);

    // branch B (default stream): layer-1 projection + fused logits
    k_gemm1<<<dim3(2, (NN + 127) / 128), 256>>>(x, W1, al1, ar1);

    // join, then fused agg1+gemm2 (6 CTAs/SM), then agg2
    cudaStreamWaitEvent(0, evCsr, 0);
    k_agg1g2<<<888, 256>>>(b1, W2, al2, ar2);
    k_reset<<<98, 512, 0, s2>>>();              // overlaps tail on s2
    cudaEventRecord(evReset, s2);
    k_agg2<<<(NN + 7) / 8, 256>>>(b2, out);
    cudaStreamWaitEvent(0, evReset, 0);         // full join for graph capture

    cudaEventDestroy(evFork);
    cudaEventDestroy(evCsr);
    cudaEventDestroy(evReset);
    cudaStreamDestroy(s2);
}